// round 1
// baseline (speedup 1.0000x reference)
#include <cuda_runtime.h>
#include <cstdint>
#include <cstddef>

// Problem constants
#define S_LEN 2048
#define I_DIM 4096
#define O_DIM 4096
#define M_DIM 8192            // B*S
#define NGRP  32              // I / 128 groups

// ---------------------------------------------------------------------------
// Scratch (device globals: no allocation allowed in kernel_launch)
// ---------------------------------------------------------------------------
__device__ __align__(16) signed char g_qx[(size_t)M_DIM * I_DIM];  // quantized activations, row-major [m][i]
__device__ __align__(16) signed char g_ws[(size_t)O_DIM * I_DIM];  // w_int - zero, row-major [o][i]

// ---------------------------------------------------------------------------
// Kernel 1: quantize activations.  q = clip(rint(x / s), -127, 127)  (int8)
// One thread per float4 (16B in / 4B out).
// ---------------------------------------------------------------------------
__global__ void quant_x_kernel(const float* __restrict__ x,
                               const float* __restrict__ act_scale) {
    int idx = blockIdx.x * blockDim.x + threadIdx.x;          // float4 index
    float4 v = reinterpret_cast<const float4*>(x)[idx];
    int m = idx >> 10;                                        // 1024 float4 per row of 4096
    float s = act_scale[m & (S_LEN - 1)];

    float r0 = rintf(__fdiv_rn(v.x, s));
    float r1 = rintf(__fdiv_rn(v.y, s));
    float r2 = rintf(__fdiv_rn(v.z, s));
    float r3 = rintf(__fdiv_rn(v.w, s));
    r0 = fmaxf(-127.f, fminf(127.f, r0));
    r1 = fmaxf(-127.f, fminf(127.f, r1));
    r2 = fmaxf(-127.f, fminf(127.f, r2));
    r3 = fmaxf(-127.f, fminf(127.f, r3));

    char4 q;
    q.x = (signed char)(int)r0;
    q.y = (signed char)(int)r1;
    q.z = (signed char)(int)r2;
    q.w = (signed char)(int)r3;
    reinterpret_cast<char4*>(g_qx)[idx] = q;
}

// ---------------------------------------------------------------------------
// Kernel 2: unpack int4 weights and subtract zero point -> int8 in [-15,15].
// qweight is (O, I/2) int32, each element holds two nibbles (low -> even i,
// high -> odd i).  One thread per int32 element.
// ---------------------------------------------------------------------------
__global__ void unpack_w_kernel(const int* __restrict__ qweight,
                                const int* __restrict__ weight_zero) {
    int idx = blockIdx.x * blockDim.x + threadIdx.x;          // 0 .. O*I/2-1
    int o = idx >> 11;                                        // 2048 int32 per row
    int j = idx & 2047;
    int v = qweight[idx];
    int z = weight_zero[o * NGRP + (j >> 6)];                 // 64 int32 per group
    char2 w;
    w.x = (signed char)((v & 15) - z);
    w.y = (signed char)(((v >> 4) & 15) - z);
    reinterpret_cast<char2*>(g_ws)[idx] = w;
}

// ---------------------------------------------------------------------------
// GEMM helpers
// ---------------------------------------------------------------------------
__device__ __forceinline__ void cp16(void* smem_dst, const void* gmem_src) {
    unsigned sa = (unsigned)__cvta_generic_to_shared(smem_dst);
    asm volatile("cp.async.cg.shared.global [%0], [%1], 16;\n" :: "r"(sa), "l"(gmem_src));
}

__device__ __forceinline__ unsigned ld32(const char* p) {
    return *reinterpret_cast<const unsigned*>(p);
}

// m16n8k32 s8 x s8 -> s32, accumulate in place
__device__ __forceinline__ void mma_s8(int* c, const unsigned* a, const unsigned* b) {
    asm volatile(
        "mma.sync.aligned.m16n8k32.row.col.s32.s8.s8.s32 "
        "{%0,%1,%2,%3},{%4,%5,%6,%7},{%8,%9},{%0,%1,%2,%3};\n"
        : "+r"(c[0]), "+r"(c[1]), "+r"(c[2]), "+r"(c[3])
        : "r"(a[0]), "r"(a[1]), "r"(a[2]), "r"(a[3]), "r"(b[0]), "r"(b[1]));
}

// ---------------------------------------------------------------------------
// Kernel 3: int8 GEMM with per-group fp32 rescale.
//   CTA tile: 128(M) x 128(N), K-slab = 128 (= one quant group)
//   256 threads = 8 warps laid out 2(M) x 4(N); warp tile 64x32
//   SMEM rows padded to 144B -> conflict-free fragment loads
//   2-stage cp.async pipeline
// ---------------------------------------------------------------------------
#define SLAB_BYTES (128 * 144)          // 18432 per tile per stage

__global__ __launch_bounds__(256, 1)
void gemm_kernel(const float* __restrict__ act_scale,
                 const float* __restrict__ wscale,     // (O, 32)
                 const float* __restrict__ bias,
                 float* __restrict__ out) {
    extern __shared__ char smem[];
    char* sA = smem;                        // [2][128*144]
    char* sB = smem + 2 * SLAB_BYTES;       // [2][128*144]

    const int bn = blockIdx.x;              // 0..31  (output cols / 128)
    const int bm = blockIdx.y;              // 0..63  (output rows / 128)
    const int tid = threadIdx.x;
    const int lane = tid & 31;
    const int wid = tid >> 5;
    const int wm = wid & 1;                 // 0..1 -> 64 rows each
    const int wn = wid >> 1;                // 0..3 -> 32 cols each

    const signed char* gA = g_qx + (size_t)bm * 128 * I_DIM;
    const signed char* gB = g_ws + (size_t)bn * 128 * I_DIM;

    float acc_f[4][4][4];
#pragma unroll
    for (int i = 0; i < 4; ++i)
#pragma unroll
        for (int j = 0; j < 4; ++j)
#pragma unroll
            for (int k = 0; k < 4; ++k) acc_f[i][j][k] = 0.f;

    // --- slab loader (both A and B tiles for group g into stage buf) ---
    auto load_slab = [&](int g, int buf) {
        char* dA = sA + buf * SLAB_BYTES;
        char* dB = sB + buf * SLAB_BYTES;
#pragma unroll
        for (int it = 0; it < 4; ++it) {
            int c = tid + it * 256;         // 0..1023
            int row = c >> 3;
            int off = (c & 7) * 16;
            cp16(dA + row * 144 + off, gA + (size_t)row * I_DIM + g * 128 + off);
            cp16(dB + row * 144 + off, gB + (size_t)row * I_DIM + g * 128 + off);
        }
    };

    load_slab(0, 0);
    asm volatile("cp.async.commit_group;\n");

    for (int g = 0; g < NGRP; ++g) {
        if (g + 1 < NGRP) {
            load_slab(g + 1, (g + 1) & 1);
            asm volatile("cp.async.commit_group;\n");
            asm volatile("cp.async.wait_group 1;\n");
        } else {
            asm volatile("cp.async.wait_group 0;\n");
        }
        __syncthreads();

        const char* cA = sA + (g & 1) * SLAB_BYTES;
        const char* cB = sB + (g & 1) * SLAB_BYTES;

        int acc_i[4][4][4];
#pragma unroll
        for (int i = 0; i < 4; ++i)
#pragma unroll
            for (int j = 0; j < 4; ++j)
#pragma unroll
                for (int k = 0; k < 4; ++k) acc_i[i][j][k] = 0;

#pragma unroll
        for (int kk = 0; kk < 4; ++kk) {
            const int ks = kk * 32;
            unsigned a[4][4];
            unsigned b[4][2];
#pragma unroll
            for (int mt = 0; mt < 4; ++mt) {
                const char* p = cA + (wm * 64 + mt * 16 + (lane >> 2)) * 144
                                   + ks + (lane & 3) * 4;
                a[mt][0] = ld32(p);
                a[mt][1] = ld32(p + 8 * 144);
                a[mt][2] = ld32(p + 16);
                a[mt][3] = ld32(p + 8 * 144 + 16);
            }
#pragma unroll
            for (int nt = 0; nt < 4; ++nt) {
                const char* p = cB + (wn * 32 + nt * 8 + (lane >> 2)) * 144
                                   + ks + (lane & 3) * 4;
                b[nt][0] = ld32(p);
                b[nt][1] = ld32(p + 16);
            }
#pragma unroll
            for (int mt = 0; mt < 4; ++mt)
#pragma unroll
                for (int nt = 0; nt < 4; ++nt)
                    mma_s8(acc_i[mt][nt], a[mt], b[nt]);
        }

        // fold exact int32 group sums into fp32 with per-(o,g) scale
#pragma unroll
        for (int nt = 0; nt < 4; ++nt) {
            int n0 = bn * 128 + wn * 32 + nt * 8 + 2 * (lane & 3);
            float s0 = __ldg(wscale + n0 * NGRP + g);
            float s1 = __ldg(wscale + n0 * NGRP + NGRP + g);   // col n0+1
#pragma unroll
            for (int mt = 0; mt < 4; ++mt) {
                acc_f[mt][nt][0] += s0 * (float)acc_i[mt][nt][0];
                acc_f[mt][nt][1] += s1 * (float)acc_i[mt][nt][1];
                acc_f[mt][nt][2] += s0 * (float)acc_i[mt][nt][2];
                acc_f[mt][nt][3] += s1 * (float)acc_i[mt][nt][3];
            }
        }
        __syncthreads();
    }

    // --- epilogue: out = s_act[m] * acc + bias[o] ---
#pragma unroll
    for (int mt = 0; mt < 4; ++mt) {
        int r0 = bm * 128 + wm * 64 + mt * 16 + (lane >> 2);
        float sa0 = act_scale[r0 & (S_LEN - 1)];
        float sa1 = act_scale[(r0 + 8) & (S_LEN - 1)];
#pragma unroll
        for (int nt = 0; nt < 4; ++nt) {
            int c0 = bn * 128 + wn * 32 + nt * 8 + 2 * (lane & 3);
            float b0 = bias[c0];
            float b1 = bias[c0 + 1];
            float2 v0, v1;
            v0.x = sa0 * acc_f[mt][nt][0] + b0;
            v0.y = sa0 * acc_f[mt][nt][1] + b1;
            v1.x = sa1 * acc_f[mt][nt][2] + b0;
            v1.y = sa1 * acc_f[mt][nt][3] + b1;
            *reinterpret_cast<float2*>(&out[(size_t)r0 * O_DIM + c0]) = v0;
            *reinterpret_cast<float2*>(&out[(size_t)(r0 + 8) * O_DIM + c0]) = v1;
        }
    }
}

// ---------------------------------------------------------------------------
// Launch.  Inputs (metadata order): x, qweight, act_scale, weight_scale,
// weight_zero, bias.  Output: float32 (B, S, O).
// ---------------------------------------------------------------------------
extern "C" void kernel_launch(void* const* d_in, const int* in_sizes, int n_in,
                              void* d_out, int out_size) {
    const float* x        = (const float*)d_in[0];
    const int*   qweight  = (const int*)d_in[1];
    const float* actscale = (const float*)d_in[2];
    const float* wscale   = (const float*)d_in[3];
    const int*   wzero    = (const int*)d_in[4];
    const float* bias     = (const float*)d_in[5];
    float* out = (float*)d_out;

    // 8192*4096/4 float4 = 8,388,608 -> 32768 blocks of 256
    quant_x_kernel<<<32768, 256>>>(x, actscale);
    // 4096*2048 int32 = 8,388,608 -> 32768 blocks of 256
    unpack_w_kernel<<<32768, 256>>>(qweight, wzero);

    cudaFuncSetAttribute(gemm_kernel,
                         cudaFuncAttributeMaxDynamicSharedMemorySize,
                         4 * SLAB_BYTES);
    dim3 grid(O_DIM / 128, M_DIM / 128);   // (32, 64); bn fastest for B-tile L2 reuse
    gemm_kernel<<<grid, 256, 4 * SLAB_BYTES>>>(actscale, wscale, bias, out);
}

// round 3
// speedup vs baseline: 1.3622x; 1.3622x over previous
#include <cuda_runtime.h>
#include <cstdint>
#include <cstddef>

// Problem constants
#define S_LEN 2048
#define I_DIM 4096
#define O_DIM 4096
#define M_DIM 8192            // B*S
#define NGRP  32              // I / 128 groups

// ---------------------------------------------------------------------------
// Scratch (device globals)
// ---------------------------------------------------------------------------
__device__ __align__(16) signed char g_qx[(size_t)M_DIM * I_DIM];  // quantized acts [m][i]
__device__ __align__(16) signed char g_ws[(size_t)O_DIM * I_DIM];  // w_int - zero   [o][i]

// ---------------------------------------------------------------------------
// Kernel 1: quantize activations. q = clip(rint(x / s), -127, 127) (int8)
// ---------------------------------------------------------------------------
__global__ void quant_x_kernel(const float* __restrict__ x,
                               const float* __restrict__ act_scale) {
    int idx = blockIdx.x * blockDim.x + threadIdx.x;          // float4 index
    float4 v = reinterpret_cast<const float4*>(x)[idx];
    int m = idx >> 10;                                        // 1024 float4 per row
    float s = act_scale[m & (S_LEN - 1)];

    float r0 = rintf(__fdiv_rn(v.x, s));
    float r1 = rintf(__fdiv_rn(v.y, s));
    float r2 = rintf(__fdiv_rn(v.z, s));
    float r3 = rintf(__fdiv_rn(v.w, s));
    r0 = fmaxf(-127.f, fminf(127.f, r0));
    r1 = fmaxf(-127.f, fminf(127.f, r1));
    r2 = fmaxf(-127.f, fminf(127.f, r2));
    r3 = fmaxf(-127.f, fminf(127.f, r3));

    char4 q;
    q.x = (signed char)(int)r0;
    q.y = (signed char)(int)r1;
    q.z = (signed char)(int)r2;
    q.w = (signed char)(int)r3;
    reinterpret_cast<char4*>(g_qx)[idx] = q;
}

// ---------------------------------------------------------------------------
// Kernel 2: unpack int4 weights, subtract zero -> int8 in [-15,15].
// One thread per int4 (4 packed int32 -> 8 int8 = uint2 store).
// ---------------------------------------------------------------------------
__global__ void unpack_w_kernel(const int* __restrict__ qweight,
                                const int* __restrict__ weight_zero) {
    int idx = blockIdx.x * blockDim.x + threadIdx.x;          // int4 index, 0..O*I/8-1
    int o = idx >> 9;                                         // 512 int4 per row
    int j4 = idx & 511;                                       // int4 within row
    int grp = j4 >> 4;                                        // 16 int4 per group
    int z = weight_zero[o * NGRP + grp];
    int4 v = reinterpret_cast<const int4*>(qweight)[idx];
    signed char w[8];
    w[0] = (signed char)((v.x & 15) - z);  w[1] = (signed char)(((v.x >> 4) & 15) - z);
    w[2] = (signed char)((v.y & 15) - z);  w[3] = (signed char)(((v.y >> 4) & 15) - z);
    w[4] = (signed char)((v.z & 15) - z);  w[5] = (signed char)(((v.z >> 4) & 15) - z);
    w[6] = (signed char)((v.w & 15) - z);  w[7] = (signed char)(((v.w >> 4) & 15) - z);
    reinterpret_cast<uint2*>(g_ws)[idx] = *reinterpret_cast<uint2*>(w);
}

// ---------------------------------------------------------------------------
// GEMM helpers
// ---------------------------------------------------------------------------
__device__ __forceinline__ void cp16(unsigned smem_dst, const void* gmem_src) {
    asm volatile("cp.async.cg.shared.global [%0], [%1], 16;\n" :: "r"(smem_dst), "l"(gmem_src));
}

__device__ __forceinline__ void ldsm4(unsigned& r0, unsigned& r1, unsigned& r2,
                                      unsigned& r3, unsigned addr) {
    asm volatile("ldmatrix.sync.aligned.m8n8.x4.shared.b16 {%0,%1,%2,%3}, [%4];"
                 : "=r"(r0), "=r"(r1), "=r"(r2), "=r"(r3) : "r"(addr));
}

__device__ __forceinline__ void mma_s8(int* c, const unsigned* a, const unsigned* b) {
    asm volatile(
        "mma.sync.aligned.m16n8k32.row.col.s32.s8.s8.s32 "
        "{%0,%1,%2,%3},{%4,%5,%6,%7},{%8,%9},{%0,%1,%2,%3};\n"
        : "+r"(c[0]), "+r"(c[1]), "+r"(c[2]), "+r"(c[3])
        : "r"(a[0]), "r"(a[1]), "r"(a[2]), "r"(a[3]), "r"(b[0]), "r"(b[1]));
}

// ---------------------------------------------------------------------------
// Kernel 3: int8 GEMM, CTA 128x128, K-slab 128 (= one group), 512 threads.
//   16 warps as 4(M) x 4(N), warp tile 32x32.
//   SMEM: 128B rows, XOR-16B swizzle -> conflict-free ldmatrix.
//   2-stage cp.async pipeline; per-group fp32 rescale from SMEM-staged wscale.
// ---------------------------------------------------------------------------
#define SMEM_STAGE 32768                   // A 16KB + B 16KB
#define SMEM_SCALE (2 * SMEM_STAGE)        // 16KB wscale (128 cols x 32 groups)
#define SMEM_TOTAL (SMEM_SCALE + 16384)

__global__ __launch_bounds__(512, 1)
void gemm_kernel(const float* __restrict__ act_scale,
                 const float* __restrict__ wscale,     // (O, 32)
                 const float* __restrict__ bias,
                 float* __restrict__ out) {
    extern __shared__ char smem[];
    const unsigned smem_base = (unsigned)__cvta_generic_to_shared(smem);

    const int bn = blockIdx.x;              // 0..31
    const int bm = blockIdx.y;              // 0..63
    const int tid = threadIdx.x;
    const int lane = tid & 31;
    const int wid = tid >> 5;
    const int wm = wid >> 2;                // 0..3 (M)
    const int wn = wid & 3;                 // 0..3 (N)

    const signed char* gA = g_qx + (size_t)bm * 128 * I_DIM;
    const signed char* gB = g_ws + (size_t)bn * 128 * I_DIM;

    // stage wscale for this CTA's 128 cols: sScale[c*32+g]
    float* sScale = reinterpret_cast<float*>(smem + SMEM_SCALE);
    {
        const float4* src = reinterpret_cast<const float4*>(wscale + (size_t)bn * 128 * NGRP);
        float4* dst = reinterpret_cast<float4*>(sScale);
        dst[tid] = src[tid];
        dst[tid + 512] = src[tid + 512];
    }

    // --- slab loader ---
    auto load_slab = [&](int g, int buf) {
        unsigned dA = smem_base + buf * SMEM_STAGE;
        unsigned dB = dA + 16384;
        const char* sAg = reinterpret_cast<const char*>(gA) + g * 128;
        const char* sBg = reinterpret_cast<const char*>(gB) + g * 128;
#pragma unroll
        for (int it = 0; it < 2; ++it) {
            int c = tid + it * 512;         // 0..1023
            int row = c >> 3, unit = c & 7;
            unsigned off = row * 128 + ((unit ^ (row & 7)) << 4);
            cp16(dA + off, sAg + (size_t)row * I_DIM + unit * 16);
            cp16(dB + off, sBg + (size_t)row * I_DIM + unit * 16);
        }
    };

    load_slab(0, 0);
    asm volatile("cp.async.commit_group;\n");

    // per-lane ldmatrix address components
    const int selA_row = ((lane >> 3) & 1) * 8 + (lane & 7);
    const int bhA = lane >> 4;              // 0/1 : 16B half of k32
    const int selB_row = ((lane >> 4) & 1) * 8 + (lane & 7);
    const int bhB = (lane >> 3) & 1;

    float acc_f[2][4][4];
#pragma unroll
    for (int i = 0; i < 2; ++i)
#pragma unroll
        for (int j = 0; j < 4; ++j)
#pragma unroll
            for (int k = 0; k < 4; ++k) acc_f[i][j][k] = 0.f;

    __syncthreads();                        // sScale visible

    for (int g = 0; g < NGRP; ++g) {
        if (g + 1 < NGRP) {
            load_slab(g + 1, (g + 1) & 1);
            asm volatile("cp.async.commit_group;\n");
            asm volatile("cp.async.wait_group 1;\n");
        } else {
            asm volatile("cp.async.wait_group 0;\n");
        }
        __syncthreads();                    // slab g visible everywhere

        const unsigned aBase = smem_base + (g & 1) * SMEM_STAGE;
        const unsigned bBase = aBase + 16384;

        int acc_i[2][4][4];
#pragma unroll
        for (int i = 0; i < 2; ++i)
#pragma unroll
            for (int j = 0; j < 4; ++j)
#pragma unroll
                for (int k = 0; k < 4; ++k) acc_i[i][j][k] = 0;

#pragma unroll
        for (int kk = 0; kk < 4; ++kk) {
            unsigned a[2][4];
            unsigned b[4][2];
#pragma unroll
            for (int mt = 0; mt < 2; ++mt) {
                int row = wm * 32 + mt * 16 + selA_row;
                unsigned slot = (unsigned)((kk * 2 + bhA) ^ (row & 7));
                ldsm4(a[mt][0], a[mt][1], a[mt][2], a[mt][3],
                      aBase + row * 128 + (slot << 4));
            }
#pragma unroll
            for (int p = 0; p < 2; ++p) {   // nt pair p -> nt 2p, 2p+1
                int row = wn * 32 + p * 16 + selB_row;
                unsigned slot = (unsigned)((kk * 2 + bhB) ^ (row & 7));
                ldsm4(b[2 * p][0], b[2 * p][1], b[2 * p + 1][0], b[2 * p + 1][1],
                      bBase + row * 128 + (slot << 4));
            }
#pragma unroll
            for (int mt = 0; mt < 2; ++mt)
#pragma unroll
                for (int nt = 0; nt < 4; ++nt)
                    mma_s8(acc_i[mt][nt], a[mt], b[nt]);
        }

        // fold exact int32 group sums with per-(col,group) scale
#pragma unroll
        for (int nt = 0; nt < 4; ++nt) {
            int c0 = wn * 32 + nt * 8 + 2 * (lane & 3);
            float s0 = sScale[c0 * NGRP + g];
            float s1 = sScale[(c0 + 1) * NGRP + g];
#pragma unroll
            for (int mt = 0; mt < 2; ++mt) {
                acc_f[mt][nt][0] += s0 * (float)acc_i[mt][nt][0];
                acc_f[mt][nt][1] += s1 * (float)acc_i[mt][nt][1];
                acc_f[mt][nt][2] += s0 * (float)acc_i[mt][nt][2];
                acc_f[mt][nt][3] += s1 * (float)acc_i[mt][nt][3];
            }
        }
        __syncthreads();                    // stage reusable
    }

    // --- epilogue: out = s_act[m] * acc + bias[o] ---
#pragma unroll
    for (int mt = 0; mt < 2; ++mt) {
        int r0 = bm * 128 + wm * 32 + mt * 16 + (lane >> 2);
        float sa0 = __ldg(act_scale + (r0 & (S_LEN - 1)));
        float sa1 = __ldg(act_scale + ((r0 + 8) & (S_LEN - 1)));
#pragma unroll
        for (int nt = 0; nt < 4; ++nt) {
            int c0 = bn * 128 + wn * 32 + nt * 8 + 2 * (lane & 3);
            float b0 = __ldg(bias + c0);
            float b1 = __ldg(bias + c0 + 1);
            float2 v0, v1;
            v0.x = sa0 * acc_f[mt][nt][0] + b0;
            v0.y = sa0 * acc_f[mt][nt][1] + b1;
            v1.x = sa1 * acc_f[mt][nt][2] + b0;
            v1.y = sa1 * acc_f[mt][nt][3] + b1;
            *reinterpret_cast<float2*>(&out[(size_t)r0 * O_DIM + c0]) = v0;
            *reinterpret_cast<float2*>(&out[(size_t)(r0 + 8) * O_DIM + c0]) = v1;
        }
    }
}

// ---------------------------------------------------------------------------
// Launch. Inputs: x, qweight, act_scale, weight_scale, weight_zero, bias.
// ---------------------------------------------------------------------------
extern "C" void kernel_launch(void* const* d_in, const int* in_sizes, int n_in,
                              void* d_out, int out_size) {
    const float* x        = (const float*)d_in[0];
    const int*   qweight  = (const int*)d_in[1];
    const float* actscale = (const float*)d_in[2];
    const float* wscale   = (const float*)d_in[3];
    const int*   wzero    = (const int*)d_in[4];
    const float* bias     = (const float*)d_in[5];
    float* out = (float*)d_out;

    quant_x_kernel<<<32768, 256>>>(x, actscale);
    // O*I/8 int4 = 2,097,152 -> 8192 blocks of 256
    unpack_w_kernel<<<8192, 256>>>(qweight, wzero);

    cudaFuncSetAttribute(gemm_kernel,
                         cudaFuncAttributeMaxDynamicSharedMemorySize, SMEM_TOTAL);
    dim3 grid(O_DIM / 128, M_DIM / 128);   // (32, 64); bn fastest for B-tile L2 reuse
    gemm_kernel<<<grid, 512, SMEM_TOTAL>>>(actscale, wscale, bias, out);
}